// round 12
// baseline (speedup 1.0000x reference)
#include <cuda_runtime.h>
#include <math.h>

// Problem constants: H_IN=W_IN=1024, STRIDE=4 -> 256x256 grid,
// B=16, C_sal=32, NUM_CLS=2, N targets=256.
#define FH 256
#define FW 256
#define HWC 65536          // FH*FW
#define BDIM 16
#define TOTAL (BDIM*HWC)   // 1,048,576 cells
#define TOTAL4 (TOTAL/4)   // 262,144 work items (4 cells each)
#define GRID_MAIN 760      // 152 SMs * 5 CTAs -> exactly one wave on GB300
#define EPSF 1e-7f
#define RAD 12             // gaussian window radius: exp(-144/4.5)=1.3e-14

// Scratch (no allocations allowed). ZERO is the "empty" state for everything:
// g_win stores prio+1 (0 = no winner), g_mask stores float bits of gauss >= 0.
// k_main restores touched cells to zero; k_pos resets accumulators/counter, so
// every graph replay sees identical initial state -> deterministic.
__device__ int          g_win[TOTAL];     // 4 MB
__device__ unsigned int g_mask[TOTAL];    // 4 MB
__device__ double       g_acc[4];         // [0]=attn_sse [1]=conf
__device__ unsigned int g_pos_cnt;        // positive-cell counter (== npos)
__device__ unsigned int g_pos[4096];      // packed (cell_idx<<12 | win)

// ---------------------------------------------------------------------------
// One block per target: assignment candidates (10 atomicMax of prio+1) +
// truncated gaussian scatter (25x25 window, atomicMax on float bits).
__global__ void k_scatter(const float* __restrict__ tg) {
    int n = blockIdx.x;
    float cx = tg[n * 6 + 1], cy = tg[n * 6 + 2];
    float w  = tg[n * 6 + 3], h  = tg[n * 6 + 4];
    int b = (int)tg[n * 6 + 0];
    int base = b * HWC;
    int t = threadIdx.x;

    if (t < 10) {
        int gi = (int)(cx * (float)FW);
        int gj = (int)(cy * (float)FH);
        int cell;
        bool valid;
        if (t < 9) {
            int nx = gi + (t / 3) - 1;
            int ny = gj + (t % 3) - 1;
            valid = (nx >= 0 && nx < FW && ny >= 0 && ny < FH);
            if (valid) {
                float ccx = ((float)nx + 0.5f) / (float)FW;
                float ccy = ((float)ny + 0.5f) / (float)FH;
                valid = (fabsf(ccx - cx) <= w * 0.5f) && (fabsf(ccy - cy) <= h * 0.5f);
            }
            cell = ny * FW + nx;
        } else {
            cell = min(gj, FH - 1) * FW + min(gi, FW - 1);
            valid = true;
        }
        if (valid) atomicMax(&g_win[base + cell], n * 10 + t + 1);  // +1: 0 = empty
    }

    float tx = cx * (float)FW, ty = cy * (float)FH;
    int x0 = max(0, (int)tx - RAD), x1 = min(FW - 1, (int)tx + RAD);
    int y0 = max(0, (int)ty - RAD), y1 = min(FH - 1, (int)ty + RAD);
    int nx = x1 - x0 + 1;
    int tot = nx * (y1 - y0 + 1);
    for (int k = t; k < tot; k += blockDim.x) {
        int x = x0 + k % nx;
        int y = y0 + k / nx;
        float dx = (float)x - tx, dy = (float)y - ty;
        float g = __expf(-(dx * dx + dy * dy) * (1.0f / 4.5f));  // 2*SIGMA^2 = 4.5
        atomicMax(&g_mask[base + y * FW + x], __float_as_uint(g));
    }
}

// ---------------------------------------------------------------------------
__device__ __forceinline__ float sigm(float x)  { return 1.0f / (1.0f + expf(-x)); }
__device__ __forceinline__ float softp(float x) { return fmaxf(x, 0.0f) + log1pf(expf(-fabsf(x))); }

// Lean streaming pass: attn SSE + focal conf + positive compaction only.
// Persistent wave-balanced grid: each block owns a contiguous equal range.
__global__ void __launch_bounds__(256, 5)
k_main(const float* __restrict__ raw, const float* __restrict__ sal) {
    int nb    = gridDim.x;
    int per   = TOTAL4 / nb;
    int rem   = TOTAL4 - per * nb;
    int start = blockIdx.x * per + min(blockIdx.x, rem);
    int count = per + (blockIdx.x < rem ? 1 : 0);

    float attn = 0.f, conf_s = 0.f;

    for (int k = threadIdx.x; k < count; k += 256) {
        int idx0 = (start + k) * 4;

        int4  winv = *(const int4*)(g_win + idx0);
        uint4 mv   = *(const uint4*)(g_mask + idx0);

        // restore scratch to all-zero (sparse predicated stores) for next replay
        if (winv.x | winv.y | winv.z | winv.w)
            *(int4*)(g_win + idx0) = make_int4(0, 0, 0, 0);
        if (mv.x | mv.y | mv.z | mv.w)
            *(uint4*)(g_mask + idx0) = make_uint4(0u, 0u, 0u, 0u);

        // conf logits: channel 4 of 7 (scalar loads; sectors dense at stride 28B)
        const float* rz = raw + (size_t)idx0 * 7 + 4;
        float zs[4] = {__ldg(rz), __ldg(rz + 7), __ldg(rz + 14), __ldg(rz + 21)};

        int b = idx0 >> 16;            // / HWC
        int i = idx0 & (HWC - 1);
        const float* sb = sal + (size_t)b * 32 * HWC + i;
        float4 s0 = make_float4(0.f, 0.f, 0.f, 0.f);
        float4 s1 = make_float4(0.f, 0.f, 0.f, 0.f);
#pragma unroll
        for (int c = 0; c < 32; c += 2) {
            float4 v0 = *(const float4*)(sb + (size_t)c * HWC);
            float4 v1 = *(const float4*)(sb + (size_t)(c + 1) * HWC);
            s0.x += v0.x; s0.y += v0.y; s0.z += v0.z; s0.w += v0.w;
            s1.x += v1.x; s1.y += v1.y; s1.z += v1.z; s1.w += v1.w;
        }
        float sals[4]  = {s0.x + s1.x, s0.y + s1.y, s0.z + s1.z, s0.w + s1.w};
        int   wins[4]  = {winv.x, winv.y, winv.z, winv.w};
        float masks[4] = {__uint_as_float(mv.x), __uint_as_float(mv.y),
                          __uint_as_float(mv.z), __uint_as_float(mv.w)};

#pragma unroll
        for (int j = 0; j < 4; j++) {
            float sm = sals[j] * (1.0f / 32.0f);
            float dm = sm - masks[j];
            attn += dm * dm;

            int  win = wins[j];
            bool obj = (win > 0);

            float z4   = zs[j];
            float conf = sigm(z4);
            float bce  = obj ? softp(-z4) : softp(z4);
            float pt   = obj ? conf : 1.0f - conf;
            float at   = obj ? 0.25f : 0.75f;
            float om   = 1.0f - pt;
            conf_s += at * om * om * bce;

            if (obj) {
                unsigned slot = atomicAdd(&g_pos_cnt, 1u);
                g_pos[slot] = ((unsigned)(idx0 + j) << 12) | (unsigned)win;
            }
        }
    }

    // block reduction: warp shuffle -> shared -> double atomicAdd
    float vals[2] = {attn, conf_s};
#pragma unroll
    for (int q = 0; q < 2; q++) {
        float v = vals[q];
#pragma unroll
        for (int o = 16; o > 0; o >>= 1) v += __shfl_xor_sync(0xffffffffu, v, o);
        vals[q] = v;
    }
    __shared__ float sh[2][8];
    int lane = threadIdx.x & 31, wid = threadIdx.x >> 5;
    if (lane == 0) { sh[0][wid] = vals[0]; sh[1][wid] = vals[1]; }
    __syncthreads();
    if (threadIdx.x == 0) {
#pragma unroll
        for (int q = 0; q < 2; q++) {
            double s = 0.0;
#pragma unroll
            for (int ww = 0; ww < 8; ww++) s += (double)sh[q][ww];
            atomicAdd(&g_acc[q], s);
        }
    }
}

// ---------------------------------------------------------------------------
// Positive-cell pass (<= 2560 entries): CIoU + CE, finalize, state reset.
__global__ void __launch_bounds__(256)
k_pos(const float* __restrict__ raw, const float* __restrict__ tg,
      float* __restrict__ out) {
    int cnt = (int)g_pos_cnt;
    float ciou_s = 0.f, cls_s = 0.f;

    for (int e = threadIdx.x; e < cnt; e += 256) {
        unsigned pk  = g_pos[e];
        int      idx = (int)(pk >> 12);
        int      win = (int)(pk & 0xFFFu);
        int      n   = (win - 1) / 10;

        const float* rr = raw + (size_t)idx * 7;
        float z0 = rr[0], z1 = rr[1], z2 = rr[2], z3 = rr[3];
        float z5 = rr[5], z6 = rr[6];

        float tcx = tg[n * 6 + 1], tcy = tg[n * 6 + 2];
        float tw  = tg[n * 6 + 3], th  = tg[n * 6 + 4];
        int   cls = (int)tg[n * 6 + 5];

        int cell = idx & (HWC - 1);
        int gx = cell & (FW - 1);
        int gy = cell >> 8;

        float pcx = (sigm(z0) + (float)gx) / (float)FW;
        float pcy = (sigm(z1) + (float)gy) / (float)FH;
        float pw  = expf(fminf(fmaxf(z2, -4.0f), 4.0f)) / (float)FW;
        float ph  = expf(fminf(fmaxf(z3, -4.0f), 4.0f)) / (float)FH;

        float px1 = pcx - pw * 0.5f, px2 = pcx + pw * 0.5f;
        float py1 = pcy - ph * 0.5f, py2 = pcy + ph * 0.5f;
        float tx1 = tcx - tw * 0.5f, tx2 = tcx + tw * 0.5f;
        float ty1 = tcy - th * 0.5f, ty2 = tcy + th * 0.5f;
        float iw = fmaxf(fminf(px2, tx2) - fmaxf(px1, tx1), 0.0f);
        float ih = fmaxf(fminf(py2, ty2) - fmaxf(py1, ty1), 0.0f);
        float inter = iw * ih;
        float uni   = pw * ph + tw * th - inter;
        float iou   = inter / (uni + EPSF);
        float cw  = fmaxf(px2, tx2) - fminf(px1, tx1);
        float chh = fmaxf(py2, ty2) - fminf(py1, ty1);
        float c2  = cw * cw + chh * chh + EPSF;
        float dd  = (pcx - tcx) * (pcx - tcx) + (pcy - tcy) * (pcy - tcy);
        float dv  = atanf(tw / (th + EPSF)) - atanf(pw / (ph + EPSF));
        float v   = 0.4052847345693511f * dv * dv;   // 4/pi^2
        float alpha = v / (1.0f - iou + v + EPSF);
        ciou_s += 1.0f - iou + dd / c2 + alpha * v;

        float m   = fmaxf(z5, z6);
        float lse = m + logf(expf(z5 - m) + expf(z6 - m));
        float zc  = (cls == 0) ? z5 : z6;
        cls_s += lse - zc;
    }

    // block reduction
#pragma unroll
    for (int o = 16; o > 0; o >>= 1) {
        ciou_s += __shfl_xor_sync(0xffffffffu, ciou_s, o);
        cls_s  += __shfl_xor_sync(0xffffffffu, cls_s,  o);
    }
    __shared__ float shc[8], shl[8];
    int lane = threadIdx.x & 31, wid = threadIdx.x >> 5;
    if (lane == 0) { shc[wid] = ciou_s; shl[wid] = cls_s; }
    __syncthreads();

    if (threadIdx.x == 0) {
        double a_ciou = 0.0, a_cls = 0.0;
#pragma unroll
        for (int ww = 0; ww < 8; ww++) { a_ciou += (double)shc[ww]; a_cls += (double)shl[ww]; }
        double norm = fmax((double)cnt, 1.0);
        double loss = 2.0 * a_ciou / norm
                    + 1.0 * g_acc[1] / norm               // conf
                    + 1.0 * a_cls  / norm
                    + 5.0 * g_acc[0] / (double)TOTAL;     // attn mean
        out[0] = (float)loss;
        // reset state for next graph replay
        g_acc[0] = 0.0; g_acc[1] = 0.0;
        g_pos_cnt = 0u;
    }
}

// ---------------------------------------------------------------------------
extern "C" void kernel_launch(void* const* d_in, const int* in_sizes, int n_in,
                              void* d_out, int out_size) {
    const float* raw = (const float*)d_in[0];   // (16, 65536, 7)
    const float* sal = (const float*)d_in[1];   // (16, 32, 256, 256)
    const float* tg  = (const float*)d_in[2];   // (256, 6)
    int N = in_sizes[2] / 6;

    k_scatter<<<N, 256>>>(tg);
    k_main<<<GRID_MAIN, 256>>>(raw, sal);
    k_pos<<<1, 256>>>(raw, tg, (float*)d_out);
}

// round 13
// speedup vs baseline: 1.1685x; 1.1685x over previous
#include <cuda_runtime.h>
#include <math.h>

// Problem constants: H_IN=W_IN=1024, STRIDE=4 -> 256x256 grid,
// B=16, C_sal=32, NUM_CLS=2, N targets=256.
#define FH 256
#define FW 256
#define HWC 65536          // FH*FW
#define BDIM 16
#define TOTAL (BDIM*HWC)   // 1,048,576 cells
#define TOTAL4 (TOTAL/4)   // 262,144 items (4 cells each)
#define GRID_MAIN (TOTAL4*2/256)  // 2048 blocks: 2 threads per item
#define POS_BLOCKS 16
#define EPSF 1e-7f
#define RAD 12             // gaussian window radius: exp(-144/4.5)=1.3e-14

// Scratch (no allocations allowed). ZERO is the "empty" state for everything:
// g_win stores prio+1 (0 = no winner), g_mask stores float bits of gauss >= 0.
// k_main restores touched cells to zero; k_pos resets accumulators/counter, so
// every graph replay sees identical initial state -> deterministic.
__device__ int          g_win[TOTAL];     // 4 MB
__device__ unsigned int g_mask[TOTAL];    // 4 MB
__device__ double       g_acc[4];         // [0]=attn [1]=conf [2]=ciou [3]=cls
__device__ unsigned int g_pos_cnt;        // positive-cell counter (== npos)
__device__ unsigned int g_pos[4096];      // packed (cell_idx<<12 | win)
__device__ unsigned int g_done;           // k_pos last-block counter (wraps to 0)

// ---------------------------------------------------------------------------
// grid (N, 4): y-block 0 also writes the 10 assignment candidates; all four
// y-blocks split the 25x25 gaussian window (atomicMax on float bits).
__global__ void k_scatter(const float* __restrict__ tg) {
    int n = blockIdx.x;
    float cx = tg[n * 6 + 1], cy = tg[n * 6 + 2];
    float w  = tg[n * 6 + 3], h  = tg[n * 6 + 4];
    int b = (int)tg[n * 6 + 0];
    int base = b * HWC;
    int t = threadIdx.x;

    if (blockIdx.y == 0 && t < 10) {
        int gi = (int)(cx * (float)FW);
        int gj = (int)(cy * (float)FH);
        int cell;
        bool valid;
        if (t < 9) {
            int nx = gi + (t / 3) - 1;
            int ny = gj + (t % 3) - 1;
            valid = (nx >= 0 && nx < FW && ny >= 0 && ny < FH);
            if (valid) {
                float ccx = ((float)nx + 0.5f) / (float)FW;
                float ccy = ((float)ny + 0.5f) / (float)FH;
                valid = (fabsf(ccx - cx) <= w * 0.5f) && (fabsf(ccy - cy) <= h * 0.5f);
            }
            cell = ny * FW + nx;
        } else {
            cell = min(gj, FH - 1) * FW + min(gi, FW - 1);
            valid = true;
        }
        if (valid) atomicMax(&g_win[base + cell], n * 10 + t + 1);  // +1: 0 = empty
    }

    float tx = cx * (float)FW, ty = cy * (float)FH;
    int x0 = max(0, (int)tx - RAD), x1 = min(FW - 1, (int)tx + RAD);
    int y0 = max(0, (int)ty - RAD), y1 = min(FH - 1, (int)ty + RAD);
    int nx = x1 - x0 + 1;
    int tot = nx * (y1 - y0 + 1);
    int k0 = (tot *  blockIdx.y)      / 4;
    int k1 = (tot * (blockIdx.y + 1)) / 4;
    for (int k = k0 + t; k < k1; k += blockDim.x) {
        int x = x0 + k % nx;
        int y = y0 + k / nx;
        float dx = (float)x - tx, dy = (float)y - ty;
        float g = __expf(-(dx * dx + dy * dy) * (1.0f / 4.5f));  // 2*SIGMA^2 = 4.5
        atomicMax(&g_mask[base + y * FW + x], __float_as_uint(g));
    }
}

// ---------------------------------------------------------------------------
__device__ __forceinline__ float sigm(float x)  { return 1.0f / (1.0f + expf(-x)); }
__device__ __forceinline__ float softp(float x) { return fmaxf(x, 0.0f) + log1pf(expf(-fabsf(x))); }

// Channel-split streaming pass: TWO threads per 4-cell item.
// even lane: sal ch 0-15 + scratch load/restore + attn + compaction
// odd  lane: sal ch 16-31 + conf logits + focal conf loss
__global__ void __launch_bounds__(256, 6)
k_main(const float* __restrict__ raw, const float* __restrict__ sal) {
    int t    = blockIdx.x * 256 + threadIdx.x;
    int pair = t >> 1;
    int half = t & 1;
    int idx0 = pair * 4;

    int b = idx0 >> 16;            // / HWC
    int i = idx0 & (HWC - 1);

    // each lane sums its 16 channels of the 4 cells
    const float* sb = sal + ((size_t)b * 32 + (half << 4)) * HWC + i;
    float4 s0 = make_float4(0.f, 0.f, 0.f, 0.f);
    float4 s1 = make_float4(0.f, 0.f, 0.f, 0.f);
#pragma unroll
    for (int c = 0; c < 16; c += 2) {
        float4 v0 = *(const float4*)(sb + (size_t)c * HWC);
        float4 v1 = *(const float4*)(sb + (size_t)(c + 1) * HWC);
        s0.x += v0.x; s0.y += v0.y; s0.z += v0.z; s0.w += v0.w;
        s1.x += v1.x; s1.y += v1.y; s1.z += v1.z; s1.w += v1.w;
    }
    float s[4] = {s0.x + s1.x, s0.y + s1.y, s0.z + s1.z, s0.w + s1.w};
#pragma unroll
    for (int j = 0; j < 4; j++)
        s[j] += __shfl_xor_sync(0xffffffffu, s[j], 1);

    // role-specific loads (predicated, no real divergence cost)
    int4  winv = make_int4(0, 0, 0, 0);
    uint4 mv   = make_uint4(0u, 0u, 0u, 0u);
    float zs[4] = {0.f, 0.f, 0.f, 0.f};
    if (half == 0) {
        winv = *(const int4*)(g_win + idx0);
        mv   = *(const uint4*)(g_mask + idx0);
        // restore scratch to zero (sparse stores) for the next replay
        if (winv.x | winv.y | winv.z | winv.w)
            *(int4*)(g_win + idx0) = make_int4(0, 0, 0, 0);
        if (mv.x | mv.y | mv.z | mv.w)
            *(uint4*)(g_mask + idx0) = make_uint4(0u, 0u, 0u, 0u);
    } else {
        const float* rz = raw + (size_t)idx0 * 7 + 4;   // conf channel
        zs[0] = __ldg(rz);      zs[1] = __ldg(rz + 7);
        zs[2] = __ldg(rz + 14); zs[3] = __ldg(rz + 21);
    }

    // broadcast win flags from even lane to its odd partner (width=2 segments)
    int wins[4] = {winv.x, winv.y, winv.z, winv.w};
#pragma unroll
    for (int j = 0; j < 4; j++)
        wins[j] = __shfl_sync(0xffffffffu, wins[j], 0, 2);

    float attn = 0.f, conf_s = 0.f;
    if (half == 0) {
        float masks[4] = {__uint_as_float(mv.x), __uint_as_float(mv.y),
                          __uint_as_float(mv.z), __uint_as_float(mv.w)};
#pragma unroll
        for (int j = 0; j < 4; j++) {
            float dm = s[j] * (1.0f / 32.0f) - masks[j];
            attn += dm * dm;
            if (wins[j] > 0) {
                unsigned slot = atomicAdd(&g_pos_cnt, 1u);
                g_pos[slot] = ((unsigned)(idx0 + j) << 12) | (unsigned)wins[j];
            }
        }
    } else {
#pragma unroll
        for (int j = 0; j < 4; j++) {
            bool  obj  = (wins[j] > 0);
            float z4   = zs[j];
            float conf = sigm(z4);
            float bce  = obj ? softp(-z4) : softp(z4);
            float pt   = obj ? conf : 1.0f - conf;
            float at   = obj ? 0.25f : 0.75f;
            float om   = 1.0f - pt;
            conf_s += at * om * om * bce;
        }
    }

    // block reduction: warp shuffle -> shared -> double atomicAdd
    float vals[2] = {attn, conf_s};
#pragma unroll
    for (int q = 0; q < 2; q++) {
        float v = vals[q];
#pragma unroll
        for (int o = 16; o > 0; o >>= 1) v += __shfl_xor_sync(0xffffffffu, v, o);
        vals[q] = v;
    }
    __shared__ float sh[2][8];
    int lane = threadIdx.x & 31, wid = threadIdx.x >> 5;
    if (lane == 0) { sh[0][wid] = vals[0]; sh[1][wid] = vals[1]; }
    __syncthreads();
    if (threadIdx.x == 0) {
#pragma unroll
        for (int q = 0; q < 2; q++) {
            double sm = 0.0;
#pragma unroll
            for (int ww = 0; ww < 8; ww++) sm += (double)sh[q][ww];
            atomicAdd(&g_acc[q], sm);
        }
    }
}

// ---------------------------------------------------------------------------
// Positive-cell pass (<= 2560 entries, 16 blocks): CIoU + CE, then the last
// block finalizes the scalar and resets all replay state.
__global__ void __launch_bounds__(256)
k_pos(const float* __restrict__ raw, const float* __restrict__ tg,
      float* __restrict__ out) {
    int cnt = (int)g_pos_cnt;
    float ciou_s = 0.f, cls_s = 0.f;

    for (int e = blockIdx.x * 256 + threadIdx.x; e < cnt; e += POS_BLOCKS * 256) {
        unsigned pk  = g_pos[e];
        int      idx = (int)(pk >> 12);
        int      win = (int)(pk & 0xFFFu);
        int      n   = (win - 1) / 10;

        const float* rr = raw + (size_t)idx * 7;
        float z0 = rr[0], z1 = rr[1], z2 = rr[2], z3 = rr[3];
        float z5 = rr[5], z6 = rr[6];

        float tcx = tg[n * 6 + 1], tcy = tg[n * 6 + 2];
        float tw  = tg[n * 6 + 3], th  = tg[n * 6 + 4];
        int   cls = (int)tg[n * 6 + 5];

        int cell = idx & (HWC - 1);
        int gx = cell & (FW - 1);
        int gy = cell >> 8;

        float pcx = (sigm(z0) + (float)gx) / (float)FW;
        float pcy = (sigm(z1) + (float)gy) / (float)FH;
        float pw  = expf(fminf(fmaxf(z2, -4.0f), 4.0f)) / (float)FW;
        float ph  = expf(fminf(fmaxf(z3, -4.0f), 4.0f)) / (float)FH;

        float px1 = pcx - pw * 0.5f, px2 = pcx + pw * 0.5f;
        float py1 = pcy - ph * 0.5f, py2 = pcy + ph * 0.5f;
        float tx1 = tcx - tw * 0.5f, tx2 = tcx + tw * 0.5f;
        float ty1 = tcy - th * 0.5f, ty2 = tcy + th * 0.5f;
        float iw = fmaxf(fminf(px2, tx2) - fmaxf(px1, tx1), 0.0f);
        float ih = fmaxf(fminf(py2, ty2) - fmaxf(py1, ty1), 0.0f);
        float inter = iw * ih;
        float uni   = pw * ph + tw * th - inter;
        float iou   = inter / (uni + EPSF);
        float cw  = fmaxf(px2, tx2) - fminf(px1, tx1);
        float chh = fmaxf(py2, ty2) - fminf(py1, ty1);
        float c2  = cw * cw + chh * chh + EPSF;
        float dd  = (pcx - tcx) * (pcx - tcx) + (pcy - tcy) * (pcy - tcy);
        float dv  = atanf(tw / (th + EPSF)) - atanf(pw / (ph + EPSF));
        float v   = 0.4052847345693511f * dv * dv;   // 4/pi^2
        float alpha = v / (1.0f - iou + v + EPSF);
        ciou_s += 1.0f - iou + dd / c2 + alpha * v;

        float m   = fmaxf(z5, z6);
        float lse = m + logf(expf(z5 - m) + expf(z6 - m));
        float zc  = (cls == 0) ? z5 : z6;
        cls_s += lse - zc;
    }

    // block reduction
#pragma unroll
    for (int o = 16; o > 0; o >>= 1) {
        ciou_s += __shfl_xor_sync(0xffffffffu, ciou_s, o);
        cls_s  += __shfl_xor_sync(0xffffffffu, cls_s,  o);
    }
    __shared__ float shc[8], shl[8];
    int lane = threadIdx.x & 31, wid = threadIdx.x >> 5;
    if (lane == 0) { shc[wid] = ciou_s; shl[wid] = cls_s; }
    __syncthreads();

    if (threadIdx.x == 0) {
        double a_ciou = 0.0, a_cls = 0.0;
#pragma unroll
        for (int ww = 0; ww < 8; ww++) { a_ciou += (double)shc[ww]; a_cls += (double)shl[ww]; }
        atomicAdd(&g_acc[2], a_ciou);
        atomicAdd(&g_acc[3], a_cls);

        __threadfence();
        unsigned rank = atomicInc(&g_done, POS_BLOCKS - 1);  // wraps to 0 on last
        if (rank == POS_BLOCKS - 1) {
            double a0 = atomicAdd(&g_acc[0], 0.0);   // attn
            double a1 = atomicAdd(&g_acc[1], 0.0);   // conf
            double a2 = atomicAdd(&g_acc[2], 0.0);   // ciou
            double a3 = atomicAdd(&g_acc[3], 0.0);   // cls
            double norm = fmax((double)cnt, 1.0);
            double loss = 2.0 * a2 / norm
                        + 1.0 * a1 / norm
                        + 1.0 * a3 / norm
                        + 5.0 * a0 / (double)TOTAL;
            out[0] = (float)loss;
            // reset state for next graph replay
            g_acc[0] = 0.0; g_acc[1] = 0.0; g_acc[2] = 0.0; g_acc[3] = 0.0;
            g_pos_cnt = 0u;
        }
    }
}

// ---------------------------------------------------------------------------
extern "C" void kernel_launch(void* const* d_in, const int* in_sizes, int n_in,
                              void* d_out, int out_size) {
    const float* raw = (const float*)d_in[0];   // (16, 65536, 7)
    const float* sal = (const float*)d_in[1];   // (16, 32, 256, 256)
    const float* tg  = (const float*)d_in[2];   // (256, 6)
    int N = in_sizes[2] / 6;

    dim3 sgrid(N, 4);
    k_scatter<<<sgrid, 256>>>(tg);
    k_main<<<GRID_MAIN, 256>>>(raw, sal);
    k_pos<<<POS_BLOCKS, 256>>>(raw, tg, (float*)d_out);
}